// round 9
// baseline (speedup 1.0000x reference)
#include <cuda_runtime.h>
#include <cuda_bf16.h>
#include <math.h>
#include <stdint.h>

#define BATCH 1024
#define FRAMES 31
#define NFFT 2048
#define N2 1024            // packed complex FFT length
#define KF 1152            // folded K: 1025 padded to 3*384
#define HID 256
#define NZ1 9              // gemm1 z: 3 terms x 3 k-chunks
#define NZ2 3              // gemm2 z: 3 terms
#define ASTR 40            // smem row stride (bf16 elems): 32 + 8 pad

// Scratch (allocation-free rule: __device__ globals)
__device__ __align__(16) __nv_bfloat16 g_a_h[BATCH * KF];
__device__ __align__(16) __nv_bfloat16 g_a_l[BATCH * KF];
__device__ __align__(16) __nv_bfloat16 g_w_h[HID * KF];
__device__ __align__(16) __nv_bfloat16 g_w_l[HID * KF];
__device__ __align__(16) __nv_bfloat16 g_w2h[HID * HID];
__device__ __align__(16) __nv_bfloat16 g_w2l[HID * HID];
__device__ __align__(16) __nv_bfloat16 g_h1h[BATCH * HID];
__device__ __align__(16) __nv_bfloat16 g_h1l[BATCH * HID];
__device__ __align__(16) float2 g_tw[N2];
__device__ __align__(16) float2 g_unt[N2 / 2 + 1];
__device__ __align__(16) float g_p1[NZ1][BATCH * HID];
__device__ __align__(16) float g_p2[NZ2][BATCH * HID];

// ---------------------------------------------------------------------------
// helpers
// ---------------------------------------------------------------------------
__device__ __forceinline__ uint32_t s2u(const void* p) {
    uint32_t a;
    asm("{ .reg .u64 t; cvta.to.shared.u64 t, %1; cvt.u32.u64 %0, t; }"
        : "=r"(a) : "l"(p));
    return a;
}
__device__ __forceinline__ void ldsm4(uint32_t& r0, uint32_t& r1, uint32_t& r2,
                                      uint32_t& r3, uint32_t addr) {
    asm volatile("ldmatrix.sync.aligned.m8n8.x4.shared.b16 {%0,%1,%2,%3}, [%4];"
                 : "=r"(r0), "=r"(r1), "=r"(r2), "=r"(r3) : "r"(addr));
}
__device__ __forceinline__ void mma_bf16(float* d, const uint32_t* a, const uint32_t* b) {
    asm volatile(
        "mma.sync.aligned.m16n8k16.row.col.f32.bf16.bf16.f32 "
        "{%0,%1,%2,%3}, {%4,%5,%6,%7}, {%8,%9}, {%0,%1,%2,%3};"
        : "+f"(d[0]), "+f"(d[1]), "+f"(d[2]), "+f"(d[3])
        : "r"(a[0]), "r"(a[1]), "r"(a[2]), "r"(a[3]), "r"(b[0]), "r"(b[1]));
}
__device__ __forceinline__ void bf_split(float v, __nv_bfloat16& h, __nv_bfloat16& l) {
    h = __float2bfloat16(v);
    l = __float2bfloat16(v - __bfloat162float(h));
}

// ---------------------------------------------------------------------------
// Prep: twiddle+untangle tables, fold+split W1, split W2. One kernel.
// ---------------------------------------------------------------------------
__global__ __launch_bounds__(256) void prep_kernel(const float* __restrict__ W1,
                                                   const float* __restrict__ W2) {
    const int idx = blockIdx.x * 256 + threadIdx.x;

    if (idx < N2) {
        float sv, cv;
        sincosf(-6.28318530717958647692f * (float)idx * (1.0f / N2), &sv, &cv);
        g_tw[idx] = make_float2(cv, sv);
    }
    if (idx <= N2 / 2) {
        float sv, cv;
        sincosf(3.14159265358979323846f * (float)idx * (1.0f / N2), &sv, &cv);
        g_unt[idx] = make_float2(cv, sv);
    }
    if (idx < HID * HID) {
        __nv_bfloat16 h, l;
        bf_split(W2[idx], h, l);
        g_w2h[idx] = h;
        g_w2l[idx] = l;
    }
    if (idx < HID * KF) {
        const int n = idx / KF;
        const int k = idx - n * KF;
        float v;
        if (k == 0)         v = W1[(size_t)n * NFFT];
        else if (k < 1024)  v = W1[(size_t)n * NFFT + k] + W1[(size_t)n * NFFT + (NFFT - k)];
        else if (k == 1024) v = W1[(size_t)n * NFFT + 1024];
        else                v = 0.f;
        __nv_bfloat16 h, l;
        bf_split(v, h, l);
        g_w_h[idx] = h;
        g_w_l[idx] = l;
    }
}

// ---------------------------------------------------------------------------
// Fused frame-mean + real-packed 1024-pt radix-4 FFT + untangle -> bf16 hi/lo.
// ---------------------------------------------------------------------------
__device__ __forceinline__ unsigned rev4_10(unsigned j) {
    unsigned r = __brev(j) >> 22;
    return ((r & 0x155u) << 1) | ((r >> 1) & 0x155u);
}

__global__ __launch_bounds__(256, 8) void fftmean_kernel(const float* __restrict__ x) {
    __shared__ float2 s[N2];        // 8 KB
    __shared__ float2 tw[N2];       // 8 KB

    const int b   = blockIdx.x;
    const int tid = threadIdx.x;
    const float4* __restrict__ p = (const float4*)x + (size_t)b * (FRAMES * NFFT / 4);

    #pragma unroll
    for (int a = tid; a < N2; a += 256) tw[a] = g_tw[a];

    const float inv = 1.0f / FRAMES;
    #pragma unroll
    for (int h = 0; h < 2; h++) {
        const int f = tid + h * 256;
        float4 acc = make_float4(0.f, 0.f, 0.f, 0.f);
        #pragma unroll
        for (int t = 0; t < FRAMES; t++) {
            float4 v = p[f + t * (NFFT / 4)];
            acc.x += v.x; acc.y += v.y; acc.z += v.z; acc.w += v.w;
        }
        s[rev4_10(2 * f)]     = make_float2(acc.x * inv, acc.y * inv);
        s[rev4_10(2 * f + 1)] = make_float2(acc.z * inv, acc.w * inv);
    }
    __syncthreads();

    #pragma unroll
    for (int st = 0; st < 5; st++) {
        const int q    = 1 << (2 * st);
        const int j    = tid & (q - 1);
        const int blk  = tid >> (2 * st);
        const int base = (blk << (2 * st + 2)) + j;
        const int e    = j << (8 - 2 * st);

        float2 x0 = s[base];
        float2 x1 = s[base + q];
        float2 x2 = s[base + 2 * q];
        float2 x3 = s[base + 3 * q];
        if (e) {
            const float2 w1 = tw[e], w2 = tw[2 * e], w3 = tw[3 * e];
            x1 = make_float2(x1.x * w1.x - x1.y * w1.y, x1.x * w1.y + x1.y * w1.x);
            x2 = make_float2(x2.x * w2.x - x2.y * w2.y, x2.x * w2.y + x2.y * w2.x);
            x3 = make_float2(x3.x * w3.x - x3.y * w3.y, x3.x * w3.y + x3.y * w3.x);
        }
        const float2 ap = make_float2(x0.x + x2.x, x0.y + x2.y);
        const float2 am = make_float2(x0.x - x2.x, x0.y - x2.y);
        const float2 bp = make_float2(x1.x + x3.x, x1.y + x3.y);
        const float2 bm = make_float2(x1.x - x3.x, x1.y - x3.y);
        s[base]         = make_float2(ap.x + bp.x, ap.y + bp.y);
        s[base + q]     = make_float2(am.x + bm.y, am.y - bm.x);
        s[base + 2 * q] = make_float2(ap.x - bp.x, ap.y - bp.y);
        s[base + 3 * q] = make_float2(am.x - bm.y, am.y + bm.x);
        __syncthreads();
    }

    __nv_bfloat16* __restrict__ oh = g_a_h + (size_t)b * KF;
    __nv_bfloat16* __restrict__ ol = g_a_l + (size_t)b * KF;
    #pragma unroll
    for (int k = tid; k <= N2 / 2; k += 256) {
        const float2 zk = s[k];
        const float2 z2 = s[(N2 - k) & (N2 - 1)];
        const float2 u  = g_unt[k];
        const float sumr = zk.x + z2.x;
        const float sumi = zk.y + z2.y;
        const float difr = zk.x - z2.x;
        float v0 = 0.5f * (sumr + u.x * sumi - u.y * difr);
        float v1 = 0.5f * (sumr - u.x * sumi + u.y * difr);
        __nv_bfloat16 h, l;
        bf_split(v0, h, l); oh[k] = h;       ol[k] = l;
        bf_split(v1, h, l); oh[N2 - k] = h;  ol[N2 - k] = l;
    }
    const __nv_bfloat16 z16 = __float2bfloat16(0.f);
    for (int k = N2 + 1 + tid; k < KF; k += 256) { oh[k] = z16; ol[k] = z16; }
}

// ---------------------------------------------------------------------------
// bf16 mma GEMM (hi/lo 3-term), generic over K stride / k-iters / k-splits.
// BM=128, BN=128, BK=32, 256 threads (8 warps, warp tile 64x32).
// ---------------------------------------------------------------------------
template <int KS, int KITERS, int KSPL>
__global__ __launch_bounds__(256) void gemm_mma_kernel(
    const __nv_bfloat16* __restrict__ Ah, const __nv_bfloat16* __restrict__ Al,
    const __nv_bfloat16* __restrict__ Wh, const __nv_bfloat16* __restrict__ Wl,
    float* __restrict__ Pbase)
{
    __shared__ __nv_bfloat16 As[2][128 * ASTR];   // 20 KB
    __shared__ __nv_bfloat16 Bs[2][128 * ASTR];   // 20 KB

    const int tid  = threadIdx.x;
    const int wid  = tid >> 5;
    const int lane = tid & 31;
    const int wm0  = (wid & 1) * 64;
    const int wn0  = (wid >> 1) * 32;
    const int m0   = blockIdx.x * 128;
    const int n0   = blockIdx.y * 128;
    const int z    = blockIdx.z;
    const int term = z / KSPL;
    const int kbeg = (z - term * KSPL) * (KITERS * 32);

    const __nv_bfloat16* __restrict__ A = (term == 1) ? Al : Ah;
    const __nv_bfloat16* __restrict__ W = (term == 2) ? Wl : Wh;

    const int a_row = (lane & 7) + ((lane >> 3) & 1) * 8;
    const int a_col = (lane >> 4) * 8;
    const int b_row = ((lane >> 4) & 1) * 8 + (lane & 7);
    const int b_col = ((lane >> 3) & 1) * 8;

    float acc[4][4][4] = {};
    uint4 rA[2], rB[2];

    #pragma unroll
    for (int i = 0; i < 2; i++) {
        const int c   = tid + i * 256;
        const int row = c >> 2;
        const int cc  = (c & 3) * 8;
        *(uint4*)&As[0][row * ASTR + cc] =
            *(const uint4*)&A[(size_t)(m0 + row) * KS + kbeg + cc];
        *(uint4*)&Bs[0][row * ASTR + cc] =
            *(const uint4*)&W[(size_t)(n0 + row) * KS + kbeg + cc];
    }

    #pragma unroll 1
    for (int it = 0; it < KITERS; it++) {
        const int cur = it & 1;
        __syncthreads();
        if (it + 1 < KITERS) {
            const int k0 = kbeg + (it + 1) * 32;
            #pragma unroll
            for (int i = 0; i < 2; i++) {
                const int c   = tid + i * 256;
                const int row = c >> 2;
                const int cc  = (c & 3) * 8;
                rA[i] = *(const uint4*)&A[(size_t)(m0 + row) * KS + k0 + cc];
                rB[i] = *(const uint4*)&W[(size_t)(n0 + row) * KS + k0 + cc];
            }
        }

        const uint32_t baseA = s2u(&As[cur][0]);
        const uint32_t baseB = s2u(&Bs[cur][0]);
        #pragma unroll
        for (int kk = 0; kk < 2; kk++) {
            uint32_t bfr[4][2];
            #pragma unroll
            for (int np = 0; np < 2; np++) {
                uint32_t r0, r1, r2, r3;
                uint32_t addr = baseB +
                    (uint32_t)(((wn0 + np * 16 + b_row) * ASTR + kk * 16 + b_col) * 2);
                ldsm4(r0, r1, r2, r3, addr);
                bfr[np * 2][0] = r0;     bfr[np * 2][1] = r1;
                bfr[np * 2 + 1][0] = r2; bfr[np * 2 + 1][1] = r3;
            }
            #pragma unroll
            for (int mi = 0; mi < 4; mi++) {
                uint32_t afr[4];
                uint32_t addr = baseA +
                    (uint32_t)(((wm0 + mi * 16 + a_row) * ASTR + kk * 16 + a_col) * 2);
                ldsm4(afr[0], afr[1], afr[2], afr[3], addr);
                #pragma unroll
                for (int ni = 0; ni < 4; ni++)
                    mma_bf16(acc[mi][ni], afr, bfr[ni]);
            }
        }

        if (it + 1 < KITERS) {
            const int nxt = cur ^ 1;
            #pragma unroll
            for (int i = 0; i < 2; i++) {
                const int c   = tid + i * 256;
                const int row = c >> 2;
                const int cc  = (c & 3) * 8;
                *(uint4*)&As[nxt][row * ASTR + cc] = rA[i];
                *(uint4*)&Bs[nxt][row * ASTR + cc] = rB[i];
            }
        }
    }

    float* __restrict__ P = Pbase + (size_t)z * (BATCH * HID);
    const int t4 = lane >> 2;
    const int t2 = (lane & 3) * 2;
    #pragma unroll
    for (int mi = 0; mi < 4; mi++) {
        const int row = m0 + wm0 + mi * 16 + t4;
        #pragma unroll
        for (int ni = 0; ni < 4; ni++) {
            const int col = n0 + wn0 + ni * 8 + t2;
            *(float2*)&P[(size_t)row * HID + col] =
                make_float2(acc[mi][ni][0], acc[mi][ni][1]);
            *(float2*)&P[(size_t)(row + 8) * HID + col] =
                make_float2(acc[mi][ni][2], acc[mi][ni][3]);
        }
    }
}

// ---------------------------------------------------------------------------
// Reduce gemm1 partials + bias + relu -> h1 bf16 hi/lo.  float4 per thread.
// grid = BATCH*HID/4/256 = 256 blocks.
// ---------------------------------------------------------------------------
__global__ __launch_bounds__(256) void reduce1_kernel(const float* __restrict__ bias) {
    const int i4 = blockIdx.x * 256 + threadIdx.x;     // 0 .. 65535
    const int n4 = i4 & (HID / 4 - 1);
    float4 v = ((const float4*)bias)[n4];
    #pragma unroll
    for (int zz = 0; zz < NZ1; zz++) {
        const float4 pv = *(const float4*)&g_p1[zz][i4 * 4];
        v.x += pv.x; v.y += pv.y; v.z += pv.z; v.w += pv.w;
    }
    v.x = fmaxf(v.x, 0.f); v.y = fmaxf(v.y, 0.f);
    v.z = fmaxf(v.z, 0.f); v.w = fmaxf(v.w, 0.f);
    __nv_bfloat16 h[4], l[4];
    bf_split(v.x, h[0], l[0]); bf_split(v.y, h[1], l[1]);
    bf_split(v.z, h[2], l[2]); bf_split(v.w, h[3], l[3]);
    *(uint2*)&g_h1h[i4 * 4] = *(uint2*)h;
    *(uint2*)&g_h1l[i4 * 4] = *(uint2*)l;
}

// ---------------------------------------------------------------------------
// Fused: reduce gemm2 partials + bias + relu + dot(W3) + sigmoid -> out.
// One warp per batch row; lane covers 8 cols (2x float4 per stream).
// grid = BATCH/8 = 128 blocks of 256 threads.
// ---------------------------------------------------------------------------
__global__ __launch_bounds__(256) void reduce2_out_kernel(
    const float* __restrict__ b2, const float* __restrict__ W3,
    const float* __restrict__ b3, float* __restrict__ out)
{
    const int warp = threadIdx.x >> 5;
    const int lane = threadIdx.x & 31;
    const int b    = blockIdx.x * 8 + warp;
    const int base = b * HID + lane * 8;

    float s = 0.f;
    #pragma unroll
    for (int half = 0; half < 2; half++) {
        const int off = base + half * 4;
        const int coff = lane * 8 + half * 4;
        float4 v  = *(const float4*)&b2[coff];
        const float4 p0 = *(const float4*)&g_p2[0][off];
        const float4 p1 = *(const float4*)&g_p2[1][off];
        const float4 p2 = *(const float4*)&g_p2[2][off];
        const float4 w  = *(const float4*)&W3[coff];
        v.x += p0.x + p1.x + p2.x;
        v.y += p0.y + p1.y + p2.y;
        v.z += p0.z + p1.z + p2.z;
        v.w += p0.w + p1.w + p2.w;
        s += fmaxf(v.x, 0.f) * w.x + fmaxf(v.y, 0.f) * w.y
           + fmaxf(v.z, 0.f) * w.z + fmaxf(v.w, 0.f) * w.w;
    }
    #pragma unroll
    for (int off = 16; off; off >>= 1) s += __shfl_down_sync(0xffffffffu, s, off);
    if (lane == 0) out[b] = 1.f / (1.f + expf(-(s + b3[0])));
}

// ---------------------------------------------------------------------------
extern "C" void kernel_launch(void* const* d_in, const int* in_sizes, int n_in,
                              void* d_out, int out_size)
{
    const float* x  = (const float*)d_in[0];
    const float* W1 = (const float*)d_in[1];
    const float* b1 = (const float*)d_in[2];
    const float* W2 = (const float*)d_in[3];
    const float* b2 = (const float*)d_in[4];
    const float* W3 = (const float*)d_in[5];
    const float* b3 = (const float*)d_in[6];
    float* out = (float*)d_out;

    __nv_bfloat16 *p_ah, *p_al, *p_wh, *p_wl, *p_w2h, *p_w2l, *p_h1h, *p_h1l;
    float *p_p1, *p_p2;
    cudaGetSymbolAddress((void**)&p_ah,  g_a_h);
    cudaGetSymbolAddress((void**)&p_al,  g_a_l);
    cudaGetSymbolAddress((void**)&p_wh,  g_w_h);
    cudaGetSymbolAddress((void**)&p_wl,  g_w_l);
    cudaGetSymbolAddress((void**)&p_w2h, g_w2h);
    cudaGetSymbolAddress((void**)&p_w2l, g_w2l);
    cudaGetSymbolAddress((void**)&p_h1h, g_h1h);
    cudaGetSymbolAddress((void**)&p_h1l, g_h1l);
    cudaGetSymbolAddress((void**)&p_p1,  g_p1);
    cudaGetSymbolAddress((void**)&p_p2,  g_p2);

    prep_kernel<<<HID * KF / 256, 256>>>(W1, W2);
    fftmean_kernel<<<BATCH, 256>>>(x);

    // layer 1: K=1152 = 3 chunks x 384 (12 iters), 3 terms -> z = 9
    dim3 g1(BATCH / 128, HID / 128, NZ1);    // (8, 2, 9) = 144 CTAs
    gemm_mma_kernel<KF, 12, 3><<<g1, 256>>>(p_ah, p_al, p_wh, p_wl, p_p1);
    reduce1_kernel<<<BATCH * HID / 4 / 256, 256>>>(b1);

    // layer 2: K=256 (8 iters), 3 terms -> z = 3
    dim3 g2(BATCH / 128, HID / 128, NZ2);    // (8, 2, 3) = 48 CTAs
    gemm_mma_kernel<HID, 8, 1><<<g2, 256>>>(p_h1h, p_h1l, p_w2h, p_w2l, p_p2);

    reduce2_out_kernel<<<BATCH / 8, 256>>>(b2, W3, b3, out);
}

// round 10
// speedup vs baseline: 1.0252x; 1.0252x over previous
#include <cuda_runtime.h>
#include <cuda_bf16.h>
#include <math.h>
#include <stdint.h>

#define BATCH 1024
#define FRAMES 31
#define NFFT 2048
#define N2 1024            // packed complex FFT length
#define KF 1152            // folded K: 1025 padded to 3*384
#define HID 256
#define NZ1 9              // gemm1 z: 3 terms x 3 k-chunks
#define NZ2 3              // gemm2 z: 3 terms
#define ASTR 40            // smem row stride (bf16 elems): 32 + 8 pad

#define W1BLKS 288         // HID*KF / 1024 elems-per-block
#define W2BLKS 64          // HID*HID / 1024

// Scratch (allocation-free rule: __device__ globals)
__device__ __align__(16) __nv_bfloat16 g_a_h[BATCH * KF];
__device__ __align__(16) __nv_bfloat16 g_a_l[BATCH * KF];
__device__ __align__(16) __nv_bfloat16 g_w_h[HID * KF];
__device__ __align__(16) __nv_bfloat16 g_w_l[HID * KF];
__device__ __align__(16) __nv_bfloat16 g_w2h[HID * HID];
__device__ __align__(16) __nv_bfloat16 g_w2l[HID * HID];
__device__ __align__(16) __nv_bfloat16 g_h1h[BATCH * HID];
__device__ __align__(16) __nv_bfloat16 g_h1l[BATCH * HID];
__device__ __align__(16) float g_p1[NZ1][BATCH * HID];
__device__ __align__(16) float g_p2[NZ2][BATCH * HID];

// ---------------------------------------------------------------------------
// helpers
// ---------------------------------------------------------------------------
__device__ __forceinline__ uint32_t s2u(const void* p) {
    uint32_t a;
    asm("{ .reg .u64 t; cvta.to.shared.u64 t, %1; cvt.u32.u64 %0, t; }"
        : "=r"(a) : "l"(p));
    return a;
}
__device__ __forceinline__ void ldsm4(uint32_t& r0, uint32_t& r1, uint32_t& r2,
                                      uint32_t& r3, uint32_t addr) {
    asm volatile("ldmatrix.sync.aligned.m8n8.x4.shared.b16 {%0,%1,%2,%3}, [%4];"
                 : "=r"(r0), "=r"(r1), "=r"(r2), "=r"(r3) : "r"(addr));
}
__device__ __forceinline__ void mma_bf16(float* d, const uint32_t* a, const uint32_t* b) {
    asm volatile(
        "mma.sync.aligned.m16n8k16.row.col.f32.bf16.bf16.f32 "
        "{%0,%1,%2,%3}, {%4,%5,%6,%7}, {%8,%9}, {%0,%1,%2,%3};"
        : "+f"(d[0]), "+f"(d[1]), "+f"(d[2]), "+f"(d[3])
        : "r"(a[0]), "r"(a[1]), "r"(a[2]), "r"(a[3]), "r"(b[0]), "r"(b[1]));
}
__device__ __forceinline__ void bf_split(float v, __nv_bfloat16& h, __nv_bfloat16& l) {
    h = __float2bfloat16(v);
    l = __float2bfloat16(v - __bfloat162float(h));
}

// ---------------------------------------------------------------------------
// Fused kernel: blocks [0,1024) = frame-mean + radix-4 rFFT + untangle;
// blocks [1024,1312) = W1 fold+split; blocks [1312,1376) = W2 split.
// Twiddle/untangle factors computed in-block (sincosf), no global tables.
// ---------------------------------------------------------------------------
__device__ __forceinline__ unsigned rev4_10(unsigned j) {
    unsigned r = __brev(j) >> 22;
    return ((r & 0x155u) << 1) | ((r >> 1) & 0x155u);
}

__global__ __launch_bounds__(256, 8) void fftmean_prep_kernel(
    const float* __restrict__ x,
    const float* __restrict__ W1, const float* __restrict__ W2)
{
    __shared__ float2 s[N2];        // 8 KB
    __shared__ float2 tw[N2];       // 8 KB

    const int tid = threadIdx.x;

    if (blockIdx.x >= BATCH) {
        const int wb = blockIdx.x - BATCH;
        if (wb < W1BLKS) {
            // W1 fold + split: 4 consecutive elems per thread
            const int idx4 = wb * 1024 + tid * 4;
            const int n = idx4 / KF;
            const int k0 = idx4 - n * KF;
            __nv_bfloat16 h[4], l[4];
            #pragma unroll
            for (int j = 0; j < 4; j++) {
                const int k = k0 + j;
                float v;
                if (k == 0)         v = W1[(size_t)n * NFFT];
                else if (k < 1024)  v = W1[(size_t)n * NFFT + k]
                                      + W1[(size_t)n * NFFT + (NFFT - k)];
                else if (k == 1024) v = W1[(size_t)n * NFFT + 1024];
                else                v = 0.f;
                bf_split(v, h[j], l[j]);
            }
            *(uint2*)&g_w_h[idx4] = *(uint2*)h;
            *(uint2*)&g_w_l[idx4] = *(uint2*)l;
        } else {
            // W2 split
            const int idx4 = (wb - W1BLKS) * 1024 + tid * 4;
            const float4 v = *(const float4*)&W2[idx4];
            __nv_bfloat16 h[4], l[4];
            bf_split(v.x, h[0], l[0]); bf_split(v.y, h[1], l[1]);
            bf_split(v.z, h[2], l[2]); bf_split(v.w, h[3], l[3]);
            *(uint2*)&g_w2h[idx4] = *(uint2*)h;
            *(uint2*)&g_w2l[idx4] = *(uint2*)l;
        }
        return;
    }

    const int b = blockIdx.x;
    const float4* __restrict__ p = (const float4*)x + (size_t)b * (FRAMES * NFFT / 4);

    // twiddles computed in-block
    #pragma unroll
    for (int a = tid; a < N2; a += 256) {
        float sv, cv;
        sincosf(-6.28318530717958647692f * (float)a * (1.0f / N2), &sv, &cv);
        tw[a] = make_float2(cv, sv);
    }

    const float inv = 1.0f / FRAMES;
    #pragma unroll
    for (int h = 0; h < 2; h++) {
        const int f = tid + h * 256;
        float4 acc = make_float4(0.f, 0.f, 0.f, 0.f);
        #pragma unroll
        for (int t = 0; t < FRAMES; t++) {
            float4 v = p[f + t * (NFFT / 4)];
            acc.x += v.x; acc.y += v.y; acc.z += v.z; acc.w += v.w;
        }
        s[rev4_10(2 * f)]     = make_float2(acc.x * inv, acc.y * inv);
        s[rev4_10(2 * f + 1)] = make_float2(acc.z * inv, acc.w * inv);
    }
    __syncthreads();

    #pragma unroll
    for (int st = 0; st < 5; st++) {
        const int q    = 1 << (2 * st);
        const int j    = tid & (q - 1);
        const int blk  = tid >> (2 * st);
        const int base = (blk << (2 * st + 2)) + j;
        const int e    = j << (8 - 2 * st);

        float2 x0 = s[base];
        float2 x1 = s[base + q];
        float2 x2 = s[base + 2 * q];
        float2 x3 = s[base + 3 * q];
        if (e) {
            const float2 w1 = tw[e], w2 = tw[2 * e], w3 = tw[3 * e];
            x1 = make_float2(x1.x * w1.x - x1.y * w1.y, x1.x * w1.y + x1.y * w1.x);
            x2 = make_float2(x2.x * w2.x - x2.y * w2.y, x2.x * w2.y + x2.y * w2.x);
            x3 = make_float2(x3.x * w3.x - x3.y * w3.y, x3.x * w3.y + x3.y * w3.x);
        }
        const float2 ap = make_float2(x0.x + x2.x, x0.y + x2.y);
        const float2 am = make_float2(x0.x - x2.x, x0.y - x2.y);
        const float2 bp = make_float2(x1.x + x3.x, x1.y + x3.y);
        const float2 bm = make_float2(x1.x - x3.x, x1.y - x3.y);
        s[base]         = make_float2(ap.x + bp.x, ap.y + bp.y);
        s[base + q]     = make_float2(am.x + bm.y, am.y - bm.x);
        s[base + 2 * q] = make_float2(ap.x - bp.x, ap.y - bp.y);
        s[base + 3 * q] = make_float2(am.x - bm.y, am.y + bm.x);
        __syncthreads();
    }

    __nv_bfloat16* __restrict__ oh = g_a_h + (size_t)b * KF;
    __nv_bfloat16* __restrict__ ol = g_a_l + (size_t)b * KF;
    #pragma unroll
    for (int k = tid; k <= N2 / 2; k += 256) {
        const float2 zk = s[k];
        const float2 z2 = s[(N2 - k) & (N2 - 1)];
        float un, uc;
        sincosf(3.14159265358979323846f * (float)k * (1.0f / N2), &un, &uc);
        const float sumr = zk.x + z2.x;
        const float sumi = zk.y + z2.y;
        const float difr = zk.x - z2.x;
        float v0 = 0.5f * (sumr + uc * sumi - un * difr);
        float v1 = 0.5f * (sumr - uc * sumi + un * difr);
        __nv_bfloat16 h, l;
        bf_split(v0, h, l); oh[k] = h;       ol[k] = l;
        bf_split(v1, h, l); oh[N2 - k] = h;  ol[N2 - k] = l;
    }
    const __nv_bfloat16 z16 = __float2bfloat16(0.f);
    for (int k = N2 + 1 + tid; k < KF; k += 256) { oh[k] = z16; ol[k] = z16; }
}

// ---------------------------------------------------------------------------
// bf16 mma GEMM (hi/lo 3-term), generic over K stride / k-iters / k-splits.
// BM=128, BN=128, BK=32, 256 threads (8 warps, warp tile 64x32).
// ---------------------------------------------------------------------------
template <int KS, int KITERS, int KSPL>
__global__ __launch_bounds__(256) void gemm_mma_kernel(
    const __nv_bfloat16* __restrict__ Ah, const __nv_bfloat16* __restrict__ Al,
    const __nv_bfloat16* __restrict__ Wh, const __nv_bfloat16* __restrict__ Wl,
    float* __restrict__ Pbase)
{
    __shared__ __nv_bfloat16 As[2][128 * ASTR];   // 20 KB
    __shared__ __nv_bfloat16 Bs[2][128 * ASTR];   // 20 KB

    const int tid  = threadIdx.x;
    const int wid  = tid >> 5;
    const int lane = tid & 31;
    const int wm0  = (wid & 1) * 64;
    const int wn0  = (wid >> 1) * 32;
    const int m0   = blockIdx.x * 128;
    const int n0   = blockIdx.y * 128;
    const int z    = blockIdx.z;
    const int term = z / KSPL;
    const int kbeg = (z - term * KSPL) * (KITERS * 32);

    const __nv_bfloat16* __restrict__ A = (term == 1) ? Al : Ah;
    const __nv_bfloat16* __restrict__ W = (term == 2) ? Wl : Wh;

    const int a_row = (lane & 7) + ((lane >> 3) & 1) * 8;
    const int a_col = (lane >> 4) * 8;
    const int b_row = ((lane >> 4) & 1) * 8 + (lane & 7);
    const int b_col = ((lane >> 3) & 1) * 8;

    float acc[4][4][4] = {};
    uint4 rA[2], rB[2];

    #pragma unroll
    for (int i = 0; i < 2; i++) {
        const int c   = tid + i * 256;
        const int row = c >> 2;
        const int cc  = (c & 3) * 8;
        *(uint4*)&As[0][row * ASTR + cc] =
            *(const uint4*)&A[(size_t)(m0 + row) * KS + kbeg + cc];
        *(uint4*)&Bs[0][row * ASTR + cc] =
            *(const uint4*)&W[(size_t)(n0 + row) * KS + kbeg + cc];
    }

    #pragma unroll 1
    for (int it = 0; it < KITERS; it++) {
        const int cur = it & 1;
        __syncthreads();
        if (it + 1 < KITERS) {
            const int k0 = kbeg + (it + 1) * 32;
            #pragma unroll
            for (int i = 0; i < 2; i++) {
                const int c   = tid + i * 256;
                const int row = c >> 2;
                const int cc  = (c & 3) * 8;
                rA[i] = *(const uint4*)&A[(size_t)(m0 + row) * KS + k0 + cc];
                rB[i] = *(const uint4*)&W[(size_t)(n0 + row) * KS + k0 + cc];
            }
        }

        const uint32_t baseA = s2u(&As[cur][0]);
        const uint32_t baseB = s2u(&Bs[cur][0]);
        #pragma unroll
        for (int kk = 0; kk < 2; kk++) {
            uint32_t bfr[4][2];
            #pragma unroll
            for (int np = 0; np < 2; np++) {
                uint32_t r0, r1, r2, r3;
                uint32_t addr = baseB +
                    (uint32_t)(((wn0 + np * 16 + b_row) * ASTR + kk * 16 + b_col) * 2);
                ldsm4(r0, r1, r2, r3, addr);
                bfr[np * 2][0] = r0;     bfr[np * 2][1] = r1;
                bfr[np * 2 + 1][0] = r2; bfr[np * 2 + 1][1] = r3;
            }
            #pragma unroll
            for (int mi = 0; mi < 4; mi++) {
                uint32_t afr[4];
                uint32_t addr = baseA +
                    (uint32_t)(((wm0 + mi * 16 + a_row) * ASTR + kk * 16 + a_col) * 2);
                ldsm4(afr[0], afr[1], afr[2], afr[3], addr);
                #pragma unroll
                for (int ni = 0; ni < 4; ni++)
                    mma_bf16(acc[mi][ni], afr, bfr[ni]);
            }
        }

        if (it + 1 < KITERS) {
            const int nxt = cur ^ 1;
            #pragma unroll
            for (int i = 0; i < 2; i++) {
                const int c   = tid + i * 256;
                const int row = c >> 2;
                const int cc  = (c & 3) * 8;
                *(uint4*)&As[nxt][row * ASTR + cc] = rA[i];
                *(uint4*)&Bs[nxt][row * ASTR + cc] = rB[i];
            }
        }
    }

    float* __restrict__ P = Pbase + (size_t)z * (BATCH * HID);
    const int t4 = lane >> 2;
    const int t2 = (lane & 3) * 2;
    #pragma unroll
    for (int mi = 0; mi < 4; mi++) {
        const int row = m0 + wm0 + mi * 16 + t4;
        #pragma unroll
        for (int ni = 0; ni < 4; ni++) {
            const int col = n0 + wn0 + ni * 8 + t2;
            *(float2*)&P[(size_t)row * HID + col] =
                make_float2(acc[mi][ni][0], acc[mi][ni][1]);
            *(float2*)&P[(size_t)(row + 8) * HID + col] =
                make_float2(acc[mi][ni][2], acc[mi][ni][3]);
        }
    }
}

// ---------------------------------------------------------------------------
// Reduce gemm1 partials + bias + relu -> h1 bf16 hi/lo.  float2 per thread.
// grid = BATCH*HID/2/256 = 512 blocks (131072 threads for latency hiding).
// ---------------------------------------------------------------------------
__global__ __launch_bounds__(256) void reduce1_kernel(const float* __restrict__ bias) {
    const int i2 = blockIdx.x * 256 + threadIdx.x;     // 0 .. 131071
    const int n2 = i2 & (HID / 2 - 1);
    float2 v = ((const float2*)bias)[n2];
    #pragma unroll
    for (int zz = 0; zz < NZ1; zz++) {
        const float2 pv = *(const float2*)&g_p1[zz][i2 * 2];
        v.x += pv.x; v.y += pv.y;
    }
    v.x = fmaxf(v.x, 0.f);
    v.y = fmaxf(v.y, 0.f);
    __nv_bfloat16 h[2], l[2];
    bf_split(v.x, h[0], l[0]);
    bf_split(v.y, h[1], l[1]);
    *(uint32_t*)&g_h1h[i2 * 2] = *(uint32_t*)h;
    *(uint32_t*)&g_h1l[i2 * 2] = *(uint32_t*)l;
}

// ---------------------------------------------------------------------------
// Fused: reduce gemm2 partials + bias + relu + dot(W3) + sigmoid -> out.
// One warp per batch row; lane covers 8 cols (2x float4 per stream).
// ---------------------------------------------------------------------------
__global__ __launch_bounds__(256) void reduce2_out_kernel(
    const float* __restrict__ b2, const float* __restrict__ W3,
    const float* __restrict__ b3, float* __restrict__ out)
{
    const int warp = threadIdx.x >> 5;
    const int lane = threadIdx.x & 31;
    const int b    = blockIdx.x * 8 + warp;
    const int base = b * HID + lane * 8;

    float s = 0.f;
    #pragma unroll
    for (int half = 0; half < 2; half++) {
        const int off = base + half * 4;
        const int coff = lane * 8 + half * 4;
        float4 v  = *(const float4*)&b2[coff];
        const float4 p0 = *(const float4*)&g_p2[0][off];
        const float4 p1 = *(const float4*)&g_p2[1][off];
        const float4 p2 = *(const float4*)&g_p2[2][off];
        const float4 w  = *(const float4*)&W3[coff];
        v.x += p0.x + p1.x + p2.x;
        v.y += p0.y + p1.y + p2.y;
        v.z += p0.z + p1.z + p2.z;
        v.w += p0.w + p1.w + p2.w;
        s += fmaxf(v.x, 0.f) * w.x + fmaxf(v.y, 0.f) * w.y
           + fmaxf(v.z, 0.f) * w.z + fmaxf(v.w, 0.f) * w.w;
    }
    #pragma unroll
    for (int off = 16; off; off >>= 1) s += __shfl_down_sync(0xffffffffu, s, off);
    if (lane == 0) out[b] = 1.f / (1.f + expf(-(s + b3[0])));
}

// ---------------------------------------------------------------------------
extern "C" void kernel_launch(void* const* d_in, const int* in_sizes, int n_in,
                              void* d_out, int out_size)
{
    const float* x  = (const float*)d_in[0];
    const float* W1 = (const float*)d_in[1];
    const float* b1 = (const float*)d_in[2];
    const float* W2 = (const float*)d_in[3];
    const float* b2 = (const float*)d_in[4];
    const float* W3 = (const float*)d_in[5];
    const float* b3 = (const float*)d_in[6];
    float* out = (float*)d_out;

    __nv_bfloat16 *p_ah, *p_al, *p_wh, *p_wl, *p_w2h, *p_w2l, *p_h1h, *p_h1l;
    float *p_p1, *p_p2;
    cudaGetSymbolAddress((void**)&p_ah,  g_a_h);
    cudaGetSymbolAddress((void**)&p_al,  g_a_l);
    cudaGetSymbolAddress((void**)&p_wh,  g_w_h);
    cudaGetSymbolAddress((void**)&p_wl,  g_w_l);
    cudaGetSymbolAddress((void**)&p_w2h, g_w2h);
    cudaGetSymbolAddress((void**)&p_w2l, g_w2l);
    cudaGetSymbolAddress((void**)&p_h1h, g_h1h);
    cudaGetSymbolAddress((void**)&p_h1l, g_h1l);
    cudaGetSymbolAddress((void**)&p_p1,  g_p1);
    cudaGetSymbolAddress((void**)&p_p2,  g_p2);

    // fused: FFT rows (1024 blocks) + W1 fold/split (288) + W2 split (64)
    fftmean_prep_kernel<<<BATCH + W1BLKS + W2BLKS, 256>>>(x, W1, W2);

    // layer 1: K=1152 = 3 chunks x 384 (12 iters), 3 terms -> z = 9
    dim3 g1(BATCH / 128, HID / 128, NZ1);    // (8, 2, 9) = 144 CTAs
    gemm_mma_kernel<KF, 12, 3><<<g1, 256>>>(p_ah, p_al, p_wh, p_wl, p_p1);
    reduce1_kernel<<<BATCH * HID / 2 / 256, 256>>>(b1);

    // layer 2: K=256 (8 iters), 3 terms -> z = 3
    dim3 g2(BATCH / 128, HID / 128, NZ2);    // (8, 2, 3) = 48 CTAs
    gemm_mma_kernel<HID, 8, 1><<<g2, 256>>>(p_h1h, p_h1l, p_w2h, p_w2l, p_p2);

    reduce2_out_kernel<<<BATCH / 8, 256>>>(b2, W3, b3, out);
}

// round 11
// speedup vs baseline: 1.0440x; 1.0183x over previous
#include <cuda_runtime.h>
#include <cuda_bf16.h>
#include <math.h>
#include <stdint.h>

#define BATCH 1024
#define FRAMES 31
#define NFFT 2048
#define N2 1024            // packed complex FFT length
#define KF 1152            // folded K: 1025 padded to 3*384
#define HID 256
#define K2C 768            // gemm2 concatenated K: [h|l|h] x [wh|wh|wl]
#define NZ1 9              // gemm1 z: 3 terms x 3 k-chunks
#define NZ2 3              // gemm2 z: 3 k-chunks of 256
#define ASTR 40            // smem row stride (bf16 elems): 32 + 8 pad

#define W1BLKS 288         // HID*KF / 1024 elems-per-block
#define W2BLKS 64          // HID*HID / 1024

// Scratch (allocation-free rule: __device__ globals)
__device__ __align__(16) __nv_bfloat16 g_a_h[BATCH * KF];
__device__ __align__(16) __nv_bfloat16 g_a_l[BATCH * KF];
__device__ __align__(16) __nv_bfloat16 g_w_h[HID * KF];
__device__ __align__(16) __nv_bfloat16 g_w_l[HID * KF];
__device__ __align__(16) __nv_bfloat16 g_w2c[HID * K2C];
__device__ __align__(16) __nv_bfloat16 g_h1c[BATCH * K2C];
__device__ __align__(16) float g_p1[NZ1][BATCH * HID];
__device__ __align__(16) float g_p2[NZ2][BATCH * HID];

// ---------------------------------------------------------------------------
// helpers
// ---------------------------------------------------------------------------
__device__ __forceinline__ uint32_t s2u(const void* p) {
    uint32_t a;
    asm("{ .reg .u64 t; cvta.to.shared.u64 t, %1; cvt.u32.u64 %0, t; }"
        : "=r"(a) : "l"(p));
    return a;
}
__device__ __forceinline__ void ldsm4(uint32_t& r0, uint32_t& r1, uint32_t& r2,
                                      uint32_t& r3, uint32_t addr) {
    asm volatile("ldmatrix.sync.aligned.m8n8.x4.shared.b16 {%0,%1,%2,%3}, [%4];"
                 : "=r"(r0), "=r"(r1), "=r"(r2), "=r"(r3) : "r"(addr));
}
__device__ __forceinline__ void mma_bf16(float* d, const uint32_t* a, const uint32_t* b) {
    asm volatile(
        "mma.sync.aligned.m16n8k16.row.col.f32.bf16.bf16.f32 "
        "{%0,%1,%2,%3}, {%4,%5,%6,%7}, {%8,%9}, {%0,%1,%2,%3};"
        : "+f"(d[0]), "+f"(d[1]), "+f"(d[2]), "+f"(d[3])
        : "r"(a[0]), "r"(a[1]), "r"(a[2]), "r"(a[3]), "r"(b[0]), "r"(b[1]));
}
__device__ __forceinline__ void bf_split(float v, __nv_bfloat16& h, __nv_bfloat16& l) {
    h = __float2bfloat16(v);
    l = __float2bfloat16(v - __bfloat162float(h));
}

// ---------------------------------------------------------------------------
// Fused kernel: blocks [0,1024) = frame-mean + radix-4 rFFT + untangle;
// blocks [1024,1312) = W1 fold+split; blocks [1312,1376) = W2 split->cat.
// ---------------------------------------------------------------------------
__device__ __forceinline__ unsigned rev4_10(unsigned j) {
    unsigned r = __brev(j) >> 22;
    return ((r & 0x155u) << 1) | ((r >> 1) & 0x155u);
}

__global__ __launch_bounds__(256, 8) void fftmean_prep_kernel(
    const float* __restrict__ x,
    const float* __restrict__ W1, const float* __restrict__ W2)
{
    __shared__ float2 s[N2];        // 8 KB
    __shared__ float2 tw[N2];       // 8 KB

    const int tid = threadIdx.x;

    if (blockIdx.x >= BATCH) {
        const int wb = blockIdx.x - BATCH;
        if (wb < W1BLKS) {
            const int idx4 = wb * 1024 + tid * 4;
            const int n = idx4 / KF;
            const int k0 = idx4 - n * KF;
            __nv_bfloat16 h[4], l[4];
            #pragma unroll
            for (int j = 0; j < 4; j++) {
                const int k = k0 + j;
                float v;
                if (k == 0)         v = W1[(size_t)n * NFFT];
                else if (k < 1024)  v = W1[(size_t)n * NFFT + k]
                                      + W1[(size_t)n * NFFT + (NFFT - k)];
                else if (k == 1024) v = W1[(size_t)n * NFFT + 1024];
                else                v = 0.f;
                bf_split(v, h[j], l[j]);
            }
            *(uint2*)&g_w_h[idx4] = *(uint2*)h;
            *(uint2*)&g_w_l[idx4] = *(uint2*)l;
        } else {
            // W2 split into concatenated [wh | wh | wl]
            const int idx4 = (wb - W1BLKS) * 1024 + tid * 4;
            const int n = idx4 >> 8;
            const int k = idx4 & 255;
            const float4 v = *(const float4*)&W2[idx4];
            __nv_bfloat16 h[4], l[4];
            bf_split(v.x, h[0], l[0]); bf_split(v.y, h[1], l[1]);
            bf_split(v.z, h[2], l[2]); bf_split(v.w, h[3], l[3]);
            const int base = n * K2C + k;
            *(uint2*)&g_w2c[base]       = *(uint2*)h;
            *(uint2*)&g_w2c[base + 256] = *(uint2*)h;
            *(uint2*)&g_w2c[base + 512] = *(uint2*)l;
        }
        return;
    }

    const int b = blockIdx.x;
    const float4* __restrict__ p = (const float4*)x + (size_t)b * (FRAMES * NFFT / 4);

    #pragma unroll
    for (int a = tid; a < N2; a += 256) {
        float sv, cv;
        sincosf(-6.28318530717958647692f * (float)a * (1.0f / N2), &sv, &cv);
        tw[a] = make_float2(cv, sv);
    }

    const float inv = 1.0f / FRAMES;
    #pragma unroll
    for (int h = 0; h < 2; h++) {
        const int f = tid + h * 256;
        float4 acc = make_float4(0.f, 0.f, 0.f, 0.f);
        #pragma unroll
        for (int t = 0; t < FRAMES; t++) {
            float4 v = p[f + t * (NFFT / 4)];
            acc.x += v.x; acc.y += v.y; acc.z += v.z; acc.w += v.w;
        }
        s[rev4_10(2 * f)]     = make_float2(acc.x * inv, acc.y * inv);
        s[rev4_10(2 * f + 1)] = make_float2(acc.z * inv, acc.w * inv);
    }
    __syncthreads();

    #pragma unroll
    for (int st = 0; st < 5; st++) {
        const int q    = 1 << (2 * st);
        const int j    = tid & (q - 1);
        const int blk  = tid >> (2 * st);
        const int base = (blk << (2 * st + 2)) + j;
        const int e    = j << (8 - 2 * st);

        float2 x0 = s[base];
        float2 x1 = s[base + q];
        float2 x2 = s[base + 2 * q];
        float2 x3 = s[base + 3 * q];
        if (e) {
            const float2 w1 = tw[e], w2 = tw[2 * e], w3 = tw[3 * e];
            x1 = make_float2(x1.x * w1.x - x1.y * w1.y, x1.x * w1.y + x1.y * w1.x);
            x2 = make_float2(x2.x * w2.x - x2.y * w2.y, x2.x * w2.y + x2.y * w2.x);
            x3 = make_float2(x3.x * w3.x - x3.y * w3.y, x3.x * w3.y + x3.y * w3.x);
        }
        const float2 ap = make_float2(x0.x + x2.x, x0.y + x2.y);
        const float2 am = make_float2(x0.x - x2.x, x0.y - x2.y);
        const float2 bp = make_float2(x1.x + x3.x, x1.y + x3.y);
        const float2 bm = make_float2(x1.x - x3.x, x1.y - x3.y);
        s[base]         = make_float2(ap.x + bp.x, ap.y + bp.y);
        s[base + q]     = make_float2(am.x + bm.y, am.y - bm.x);
        s[base + 2 * q] = make_float2(ap.x - bp.x, ap.y - bp.y);
        s[base + 3 * q] = make_float2(am.x - bm.y, am.y + bm.x);
        __syncthreads();
    }

    __nv_bfloat16* __restrict__ oh = g_a_h + (size_t)b * KF;
    __nv_bfloat16* __restrict__ ol = g_a_l + (size_t)b * KF;
    #pragma unroll
    for (int k = tid; k <= N2 / 2; k += 256) {
        const float2 zk = s[k];
        const float2 z2 = s[(N2 - k) & (N2 - 1)];
        float un, uc;
        sincosf(3.14159265358979323846f * (float)k * (1.0f / N2), &un, &uc);
        const float sumr = zk.x + z2.x;
        const float sumi = zk.y + z2.y;
        const float difr = zk.x - z2.x;
        float v0 = 0.5f * (sumr + uc * sumi - un * difr);
        float v1 = 0.5f * (sumr - uc * sumi + un * difr);
        __nv_bfloat16 h, l;
        bf_split(v0, h, l); oh[k] = h;       ol[k] = l;
        bf_split(v1, h, l); oh[N2 - k] = h;  ol[N2 - k] = l;
    }
    const __nv_bfloat16 z16 = __float2bfloat16(0.f);
    for (int k = N2 + 1 + tid; k < KF; k += 256) { oh[k] = z16; ol[k] = z16; }
}

// ---------------------------------------------------------------------------
// GEMM1: bf16 mma (hi/lo 3-term), BM=128, BN=128, BK=32, 256 thr, 8 warps.
// ---------------------------------------------------------------------------
__global__ __launch_bounds__(256, 2) void gemm1_mma_kernel(
    const __nv_bfloat16* __restrict__ Ah, const __nv_bfloat16* __restrict__ Al,
    const __nv_bfloat16* __restrict__ Wh, const __nv_bfloat16* __restrict__ Wl)
{
    const int KS = KF, KITERS = 12, KSPL = 3;
    __shared__ __nv_bfloat16 As[2][128 * ASTR];   // 20 KB
    __shared__ __nv_bfloat16 Bs[2][128 * ASTR];   // 20 KB

    const int tid  = threadIdx.x;
    const int wid  = tid >> 5;
    const int lane = tid & 31;
    const int wm0  = (wid & 1) * 64;
    const int wn0  = (wid >> 1) * 32;
    const int m0   = blockIdx.x * 128;
    const int n0   = blockIdx.y * 128;
    const int z    = blockIdx.z;
    const int term = z / KSPL;
    const int kbeg = (z - term * KSPL) * (KITERS * 32);

    const __nv_bfloat16* __restrict__ A = (term == 1) ? Al : Ah;
    const __nv_bfloat16* __restrict__ W = (term == 2) ? Wl : Wh;

    const int a_row = (lane & 7) + ((lane >> 3) & 1) * 8;
    const int a_col = (lane >> 4) * 8;
    const int b_row = ((lane >> 4) & 1) * 8 + (lane & 7);
    const int b_col = ((lane >> 3) & 1) * 8;

    float acc[4][4][4] = {};
    uint4 rA[2], rB[2];

    #pragma unroll
    for (int i = 0; i < 2; i++) {
        const int c   = tid + i * 256;
        const int row = c >> 2;
        const int cc  = (c & 3) * 8;
        *(uint4*)&As[0][row * ASTR + cc] =
            *(const uint4*)&A[(size_t)(m0 + row) * KS + kbeg + cc];
        *(uint4*)&Bs[0][row * ASTR + cc] =
            *(const uint4*)&W[(size_t)(n0 + row) * KS + kbeg + cc];
    }

    #pragma unroll 1
    for (int it = 0; it < KITERS; it++) {
        const int cur = it & 1;
        __syncthreads();
        if (it + 1 < KITERS) {
            const int k0 = kbeg + (it + 1) * 32;
            #pragma unroll
            for (int i = 0; i < 2; i++) {
                const int c   = tid + i * 256;
                const int row = c >> 2;
                const int cc  = (c & 3) * 8;
                rA[i] = *(const uint4*)&A[(size_t)(m0 + row) * KS + k0 + cc];
                rB[i] = *(const uint4*)&W[(size_t)(n0 + row) * KS + k0 + cc];
            }
        }

        const uint32_t baseA = s2u(&As[cur][0]);
        const uint32_t baseB = s2u(&Bs[cur][0]);
        #pragma unroll
        for (int kk = 0; kk < 2; kk++) {
            uint32_t bfr[4][2];
            #pragma unroll
            for (int np = 0; np < 2; np++) {
                uint32_t r0, r1, r2, r3;
                uint32_t addr = baseB +
                    (uint32_t)(((wn0 + np * 16 + b_row) * ASTR + kk * 16 + b_col) * 2);
                ldsm4(r0, r1, r2, r3, addr);
                bfr[np * 2][0] = r0;     bfr[np * 2][1] = r1;
                bfr[np * 2 + 1][0] = r2; bfr[np * 2 + 1][1] = r3;
            }
            #pragma unroll
            for (int mi = 0; mi < 4; mi++) {
                uint32_t afr[4];
                uint32_t addr = baseA +
                    (uint32_t)(((wm0 + mi * 16 + a_row) * ASTR + kk * 16 + a_col) * 2);
                ldsm4(afr[0], afr[1], afr[2], afr[3], addr);
                #pragma unroll
                for (int ni = 0; ni < 4; ni++)
                    mma_bf16(acc[mi][ni], afr, bfr[ni]);
            }
        }

        if (it + 1 < KITERS) {
            const int nxt = cur ^ 1;
            #pragma unroll
            for (int i = 0; i < 2; i++) {
                const int c   = tid + i * 256;
                const int row = c >> 2;
                const int cc  = (c & 3) * 8;
                *(uint4*)&As[nxt][row * ASTR + cc] = rA[i];
                *(uint4*)&Bs[nxt][row * ASTR + cc] = rB[i];
            }
        }
    }

    float* __restrict__ P = g_p1[z];
    const int t4 = lane >> 2;
    const int t2 = (lane & 3) * 2;
    #pragma unroll
    for (int mi = 0; mi < 4; mi++) {
        const int row = m0 + wm0 + mi * 16 + t4;
        #pragma unroll
        for (int ni = 0; ni < 4; ni++) {
            const int col = n0 + wn0 + ni * 8 + t2;
            *(float2*)&P[(size_t)row * HID + col] =
                make_float2(acc[mi][ni][0], acc[mi][ni][1]);
            *(float2*)&P[(size_t)(row + 8) * HID + col] =
                make_float2(acc[mi][ni][2], acc[mi][ni][3]);
        }
    }
}

// ---------------------------------------------------------------------------
// GEMM2: single GEMM over concatenated K=768. BM=64, BN=64, BK=32,
// 128 threads (4 warps, 32x32 warp tile), split-K 3 -> grid (16,4,3).
// ---------------------------------------------------------------------------
__global__ __launch_bounds__(128) void gemm2_mma_kernel() {
    const int KITERS = 8;
    __shared__ __nv_bfloat16 As[2][64 * ASTR];   // 10 KB
    __shared__ __nv_bfloat16 Bs[2][64 * ASTR];   // 10 KB

    const int tid  = threadIdx.x;
    const int wid  = tid >> 5;
    const int lane = tid & 31;
    const int wm0  = (wid & 1) * 32;
    const int wn0  = (wid >> 1) * 32;
    const int m0   = blockIdx.x * 64;
    const int n0   = blockIdx.y * 64;
    const int kbeg = blockIdx.z * 256;

    const int a_row = (lane & 7) + ((lane >> 3) & 1) * 8;
    const int a_col = (lane >> 4) * 8;
    const int b_row = ((lane >> 4) & 1) * 8 + (lane & 7);
    const int b_col = ((lane >> 3) & 1) * 8;

    float acc[2][4][4] = {};
    uint4 rA[2], rB[2];

    #pragma unroll
    for (int i = 0; i < 2; i++) {
        const int c   = tid + i * 128;
        const int row = c >> 2;
        const int cc  = (c & 3) * 8;
        *(uint4*)&As[0][row * ASTR + cc] =
            *(const uint4*)&g_h1c[(size_t)(m0 + row) * K2C + kbeg + cc];
        *(uint4*)&Bs[0][row * ASTR + cc] =
            *(const uint4*)&g_w2c[(size_t)(n0 + row) * K2C + kbeg + cc];
    }

    #pragma unroll 1
    for (int it = 0; it < KITERS; it++) {
        const int cur = it & 1;
        __syncthreads();
        if (it + 1 < KITERS) {
            const int k0 = kbeg + (it + 1) * 32;
            #pragma unroll
            for (int i = 0; i < 2; i++) {
                const int c   = tid + i * 128;
                const int row = c >> 2;
                const int cc  = (c & 3) * 8;
                rA[i] = *(const uint4*)&g_h1c[(size_t)(m0 + row) * K2C + k0 + cc];
                rB[i] = *(const uint4*)&g_w2c[(size_t)(n0 + row) * K2C + k0 + cc];
            }
        }

        const uint32_t baseA = s2u(&As[cur][0]);
        const uint32_t baseB = s2u(&Bs[cur][0]);
        #pragma unroll
        for (int kk = 0; kk < 2; kk++) {
            uint32_t bfr[4][2];
            #pragma unroll
            for (int np = 0; np < 2; np++) {
                uint32_t r0, r1, r2, r3;
                uint32_t addr = baseB +
                    (uint32_t)(((wn0 + np * 16 + b_row) * ASTR + kk * 16 + b_col) * 2);
                ldsm4(r0, r1, r2, r3, addr);
                bfr[np * 2][0] = r0;     bfr[np * 2][1] = r1;
                bfr[np * 2 + 1][0] = r2; bfr[np * 2 + 1][1] = r3;
            }
            #pragma unroll
            for (int mi = 0; mi < 2; mi++) {
                uint32_t afr[4];
                uint32_t addr = baseA +
                    (uint32_t)(((wm0 + mi * 16 + a_row) * ASTR + kk * 16 + a_col) * 2);
                ldsm4(afr[0], afr[1], afr[2], afr[3], addr);
                #pragma unroll
                for (int ni = 0; ni < 4; ni++)
                    mma_bf16(acc[mi][ni], afr, bfr[ni]);
            }
        }

        if (it + 1 < KITERS) {
            const int nxt = cur ^ 1;
            #pragma unroll
            for (int i = 0; i < 2; i++) {
                const int c   = tid + i * 128;
                const int row = c >> 2;
                const int cc  = (c & 3) * 8;
                *(uint4*)&As[nxt][row * ASTR + cc] = rA[i];
                *(uint4*)&Bs[nxt][row * ASTR + cc] = rB[i];
            }
        }
    }

    float* __restrict__ P = g_p2[blockIdx.z];
    const int t4 = lane >> 2;
    const int t2 = (lane & 3) * 2;
    #pragma unroll
    for (int mi = 0; mi < 2; mi++) {
        const int row = m0 + wm0 + mi * 16 + t4;
        #pragma unroll
        for (int ni = 0; ni < 4; ni++) {
            const int col = n0 + wn0 + ni * 8 + t2;
            *(float2*)&P[(size_t)row * HID + col] =
                make_float2(acc[mi][ni][0], acc[mi][ni][1]);
            *(float2*)&P[(size_t)(row + 8) * HID + col] =
                make_float2(acc[mi][ni][2], acc[mi][ni][3]);
        }
    }
}

// ---------------------------------------------------------------------------
// Reduce gemm1 partials + bias + relu -> h1cat [h | l | h].  float2/thread.
// ---------------------------------------------------------------------------
__global__ __launch_bounds__(256) void reduce1_kernel(const float* __restrict__ bias) {
    const int i2 = blockIdx.x * 256 + threadIdx.x;     // 0 .. 131071
    const int n2 = i2 & (HID / 2 - 1);
    const int row = i2 >> 7;
    float2 v = ((const float2*)bias)[n2];
    #pragma unroll
    for (int zz = 0; zz < NZ1; zz++) {
        const float2 pv = *(const float2*)&g_p1[zz][i2 * 2];
        v.x += pv.x; v.y += pv.y;
    }
    v.x = fmaxf(v.x, 0.f);
    v.y = fmaxf(v.y, 0.f);
    __nv_bfloat16 h[2], l[2];
    bf_split(v.x, h[0], l[0]);
    bf_split(v.y, h[1], l[1]);
    const int base = row * K2C + n2 * 2;
    *(uint32_t*)&g_h1c[base]       = *(uint32_t*)h;
    *(uint32_t*)&g_h1c[base + 256] = *(uint32_t*)l;
    *(uint32_t*)&g_h1c[base + 512] = *(uint32_t*)h;
}

// ---------------------------------------------------------------------------
// Fused: reduce gemm2 partials + bias + relu + dot(W3) + sigmoid -> out.
// ---------------------------------------------------------------------------
__global__ __launch_bounds__(256) void reduce2_out_kernel(
    const float* __restrict__ b2, const float* __restrict__ W3,
    const float* __restrict__ b3, float* __restrict__ out)
{
    const int warp = threadIdx.x >> 5;
    const int lane = threadIdx.x & 31;
    const int b    = blockIdx.x * 8 + warp;
    const int base = b * HID + lane * 8;

    float s = 0.f;
    #pragma unroll
    for (int half = 0; half < 2; half++) {
        const int off = base + half * 4;
        const int coff = lane * 8 + half * 4;
        float4 v  = *(const float4*)&b2[coff];
        const float4 p0 = *(const float4*)&g_p2[0][off];
        const float4 p1 = *(const float4*)&g_p2[1][off];
        const float4 p2 = *(const float4*)&g_p2[2][off];
        const float4 w  = *(const float4*)&W3[coff];
        v.x += p0.x + p1.x + p2.x;
        v.y += p0.y + p1.y + p2.y;
        v.z += p0.z + p1.z + p2.z;
        v.w += p0.w + p1.w + p2.w;
        s += fmaxf(v.x, 0.f) * w.x + fmaxf(v.y, 0.f) * w.y
           + fmaxf(v.z, 0.f) * w.z + fmaxf(v.w, 0.f) * w.w;
    }
    #pragma unroll
    for (int off = 16; off; off >>= 1) s += __shfl_down_sync(0xffffffffu, s, off);
    if (lane == 0) out[b] = 1.f / (1.f + expf(-(s + b3[0])));
}

// ---------------------------------------------------------------------------
extern "C" void kernel_launch(void* const* d_in, const int* in_sizes, int n_in,
                              void* d_out, int out_size)
{
    const float* x  = (const float*)d_in[0];
    const float* W1 = (const float*)d_in[1];
    const float* b1 = (const float*)d_in[2];
    const float* W2 = (const float*)d_in[3];
    const float* b2 = (const float*)d_in[4];
    const float* W3 = (const float*)d_in[5];
    const float* b3 = (const float*)d_in[6];
    float* out = (float*)d_out;

    __nv_bfloat16 *p_ah, *p_al, *p_wh, *p_wl;
    cudaGetSymbolAddress((void**)&p_ah, g_a_h);
    cudaGetSymbolAddress((void**)&p_al, g_a_l);
    cudaGetSymbolAddress((void**)&p_wh, g_w_h);
    cudaGetSymbolAddress((void**)&p_wl, g_w_l);

    // fused: FFT rows (1024 blocks) + W1 fold/split (288) + W2 split/cat (64)
    fftmean_prep_kernel<<<BATCH + W1BLKS + W2BLKS, 256>>>(x, W1, W2);

    // layer 1: K=1152 = 3 chunks x 384 (12 iters), 3 terms -> z = 9
    dim3 g1(BATCH / 128, HID / 128, NZ1);    // (8, 2, 9) = 144 CTAs
    gemm1_mma_kernel<<<g1, 256>>>(p_ah, p_al, p_wh, p_wl);
    reduce1_kernel<<<BATCH * HID / 2 / 256, 256>>>(b1);

    // layer 2: concatenated K=768, split-K 3 -> (16, 4, 3) = 192 CTAs
    dim3 g2(BATCH / 64, HID / 64, NZ2);
    gemm2_mma_kernel<<<g2, 128>>>();

    reduce2_out_kernel<<<BATCH / 8, 256>>>(b2, W3, b3, out);
}